// round 1
// baseline (speedup 1.0000x reference)
#include <cuda_runtime.h>
#include <cuda_bf16.h>

// ---------------------------------------------------------------------------
// TransformerBlock: B=2, S=2048, D=1024, H=16, Dk=64, Dff=4096, fp32
// Round 0: correct fp32 baseline. LN -> QKV proj -> flash attention ->
// O proj + residual -> LN -> FFN(relu) -> residual.
// ---------------------------------------------------------------------------

#define D_MODEL 1024
#define N_HEADS 16
#define D_K     64
#define D_FF    4096
#define B_      2
#define S_      2048
#define M_ROWS  (B_ * S_)          // 4096

// ---------------- scratch (device globals; no allocations allowed) ----------
__device__ float g_h  [M_ROWS * D_MODEL];
__device__ float g_q  [M_ROWS * D_MODEL];
__device__ float g_k  [M_ROWS * D_MODEL];
__device__ float g_v  [M_ROWS * D_MODEL];
__device__ float g_ctx[M_ROWS * D_MODEL];
__device__ float g_x1 [M_ROWS * D_MODEL];
__device__ float g_h2 [M_ROWS * D_MODEL];
__device__ float g_ff [M_ROWS * D_FF];

// ---------------------------------------------------------------------------
// LayerNorm: one block per row (1024 elems), 256 threads x 4 elems
// ---------------------------------------------------------------------------
__global__ __launch_bounds__(256) void layernorm_kernel(
    const float* __restrict__ x, const float* __restrict__ w,
    const float* __restrict__ b, float* __restrict__ out)
{
    int row = blockIdx.x;
    const float* xr = x + (long)row * D_MODEL;
    int c = threadIdx.x * 4;
    float4 v = *(const float4*)(xr + c);
    float s  = v.x + v.y + v.z + v.w;
    float ss = v.x*v.x + v.y*v.y + v.z*v.z + v.w*v.w;

    #pragma unroll
    for (int o = 16; o > 0; o >>= 1) {
        s  += __shfl_xor_sync(0xffffffffu, s,  o);
        ss += __shfl_xor_sync(0xffffffffu, ss, o);
    }
    __shared__ float rs[8], rss[8];
    int wid = threadIdx.x >> 5, lane = threadIdx.x & 31;
    if (lane == 0) { rs[wid] = s; rss[wid] = ss; }
    __syncthreads();
    s = 0.f; ss = 0.f;
    #pragma unroll
    for (int i = 0; i < 8; i++) { s += rs[i]; ss += rss[i]; }

    float mu  = s * (1.0f / D_MODEL);
    float var = ss * (1.0f / D_MODEL) - mu * mu;
    float rstd = rsqrtf(var + 1e-5f);

    float4 wv = *(const float4*)(w + c);
    float4 bv = *(const float4*)(b + c);
    float4 o4;
    o4.x = (v.x - mu) * rstd * wv.x + bv.x;
    o4.y = (v.y - mu) * rstd * wv.y + bv.y;
    o4.z = (v.z - mu) * rstd * wv.z + bv.z;
    o4.w = (v.w - mu) * rstd * wv.w + bv.w;
    *(float4*)(out + (long)row * D_MODEL + c) = o4;
}

// ---------------------------------------------------------------------------
// SGEMM: C[M,N] = A[M,K] @ W[K,N] + bias[N] (+res[M,N]) (+relu)
// BM=BN=128, BK=8, 256 threads, 8x8 per thread.
// ---------------------------------------------------------------------------
template<bool RELU, bool RES>
__global__ __launch_bounds__(256) void sgemm_kernel(
    const float* __restrict__ A, const float* __restrict__ W,
    const float* __restrict__ bias, const float* __restrict__ res,
    float* __restrict__ C, int M, int N, int K)
{
    const int BM = 128, BN = 128, BK = 8;
    __shared__ float As[BK][BM];
    __shared__ float Bs[BK][BN];

    int bx = blockIdx.x, by = blockIdx.y;
    int tid = threadIdx.x;
    int tx = tid & 15, ty = tid >> 4;

    float acc[8][8];
    #pragma unroll
    for (int i = 0; i < 8; i++)
        #pragma unroll
        for (int j = 0; j < 8; j++) acc[i][j] = 0.f;

    const float* Aptr = A + (long)(by * BM) * K;
    const float* Wptr = W + bx * BN;

    int arow = tid >> 1;            // 0..127
    int acol = (tid & 1) * 4;       // 0 or 4
    int brow = tid >> 5;            // 0..7
    int bcol = (tid & 31) * 4;      // 0..124

    for (int k0 = 0; k0 < K; k0 += BK) {
        float4 av = *(const float4*)(Aptr + (long)arow * K + k0 + acol);
        As[acol + 0][arow] = av.x;
        As[acol + 1][arow] = av.y;
        As[acol + 2][arow] = av.z;
        As[acol + 3][arow] = av.w;
        float4 bv = *(const float4*)(Wptr + (long)(k0 + brow) * N + bcol);
        *(float4*)&Bs[brow][bcol] = bv;
        __syncthreads();

        #pragma unroll
        for (int k = 0; k < BK; k++) {
            float ar[8], br[8];
            #pragma unroll
            for (int i = 0; i < 8; i++) ar[i] = As[k][ty * 8 + i];
            #pragma unroll
            for (int j = 0; j < 8; j++) br[j] = Bs[k][tx * 8 + j];
            #pragma unroll
            for (int i = 0; i < 8; i++)
                #pragma unroll
                for (int j = 0; j < 8; j++)
                    acc[i][j] += ar[i] * br[j];
        }
        __syncthreads();
    }

    #pragma unroll
    for (int i = 0; i < 8; i++) {
        int row = by * BM + ty * 8 + i;
        #pragma unroll
        for (int j = 0; j < 8; j += 4) {
            int col = bx * BN + tx * 8 + j;
            float4 o;
            float* po = &o.x;
            #pragma unroll
            for (int jj = 0; jj < 4; jj++) {
                float vv = acc[i][j + jj] + bias[col + jj];
                if (RES) vv += res[(long)row * N + col + jj];
                if (RELU) vv = fmaxf(vv, 0.f);
                po[jj] = vv;
            }
            *(float4*)(C + (long)row * N + col) = o;
        }
    }
}

// ---------------------------------------------------------------------------
// Flash attention: per (qblock, head, batch). BQ=64 queries, BKV=32 keys/tile.
// O accumulator in registers (4x4 per thread), online softmax in smem.
// ---------------------------------------------------------------------------
__global__ __launch_bounds__(256) void attn_kernel(
    const float* __restrict__ Q, const float* __restrict__ K,
    const float* __restrict__ V, float* __restrict__ O)
{
    const int BQ = 64, BKV = 32;
    __shared__ float Qs[BQ][D_K + 1];
    __shared__ float Ks[BKV][D_K + 1];
    __shared__ float Vs[BKV][D_K + 1];
    __shared__ float Ss[BQ][BKV + 1];
    __shared__ float m_s[BQ], l_s[BQ], a_s[BQ];

    int qb = blockIdx.x, h = blockIdx.y, b = blockIdx.z;
    int tid = threadIdx.x;
    int tx = tid & 15, ty = tid >> 4;
    const float scale = 0.125f;  // 1/sqrt(64)

    long base = ((long)b * S_) * D_MODEL + h * D_K;

    // load Q tile: 64x64, 16 floats per thread
    {
        int i  = tid >> 2;           // row 0..63
        int c4 = (tid & 3) * 4;      // 0,4,8,12
        const float* qp = Q + base + (long)(qb * BQ + i) * D_MODEL;
        #pragma unroll
        for (int u = 0; u < 4; u++) {
            float4 vv = *(const float4*)(qp + c4 + u * 16);
            Qs[i][c4 + u * 16 + 0] = vv.x;
            Qs[i][c4 + u * 16 + 1] = vv.y;
            Qs[i][c4 + u * 16 + 2] = vv.z;
            Qs[i][c4 + u * 16 + 3] = vv.w;
        }
    }
    if (tid < BQ) { m_s[tid] = -1e30f; l_s[tid] = 0.f; }

    float o[4][4];
    #pragma unroll
    for (int r = 0; r < 4; r++)
        #pragma unroll
        for (int c = 0; c < 4; c++) o[r][c] = 0.f;

    __syncthreads();

    for (int j0 = 0; j0 < S_; j0 += BKV) {
        // load K/V tiles: 32x64 each, 8 floats per thread per tensor
        {
            int row = tid >> 3;           // 0..31
            int c0  = (tid & 7) * 8;      // 0..56
            const float* kp = K + base + (long)(j0 + row) * D_MODEL;
            const float* vp = V + base + (long)(j0 + row) * D_MODEL;
            float4 k1 = *(const float4*)(kp + c0);
            float4 k2 = *(const float4*)(kp + c0 + 4);
            float4 v1 = *(const float4*)(vp + c0);
            float4 v2 = *(const float4*)(vp + c0 + 4);
            Ks[row][c0+0]=k1.x; Ks[row][c0+1]=k1.y; Ks[row][c0+2]=k1.z; Ks[row][c0+3]=k1.w;
            Ks[row][c0+4]=k2.x; Ks[row][c0+5]=k2.y; Ks[row][c0+6]=k2.z; Ks[row][c0+7]=k2.w;
            Vs[row][c0+0]=v1.x; Vs[row][c0+1]=v1.y; Vs[row][c0+2]=v1.z; Vs[row][c0+3]=v1.w;
            Vs[row][c0+4]=v2.x; Vs[row][c0+5]=v2.y; Vs[row][c0+6]=v2.z; Vs[row][c0+7]=v2.w;
        }
        __syncthreads();

        // scores: rows ty*4..+3, cols tx*2..+1
        float acc[4][2];
        #pragma unroll
        for (int r = 0; r < 4; r++) { acc[r][0] = 0.f; acc[r][1] = 0.f; }
        #pragma unroll 8
        for (int d = 0; d < D_K; d++) {
            float a0 = Qs[ty*4+0][d], a1 = Qs[ty*4+1][d];
            float a2 = Qs[ty*4+2][d], a3 = Qs[ty*4+3][d];
            float b0 = Ks[tx*2+0][d], b1 = Ks[tx*2+1][d];
            acc[0][0] += a0*b0; acc[0][1] += a0*b1;
            acc[1][0] += a1*b0; acc[1][1] += a1*b1;
            acc[2][0] += a2*b0; acc[2][1] += a2*b1;
            acc[3][0] += a3*b0; acc[3][1] += a3*b1;
        }
        #pragma unroll
        for (int r = 0; r < 4; r++) {
            Ss[ty*4+r][tx*2+0] = acc[r][0] * scale;
            Ss[ty*4+r][tx*2+1] = acc[r][1] * scale;
        }
        __syncthreads();

        // online softmax: one owner thread per query row
        if (tid < BQ) {
            float mo = m_s[tid], mn = mo;
            #pragma unroll
            for (int j = 0; j < BKV; j++) mn = fmaxf(mn, Ss[tid][j]);
            float al = __expf(mo - mn);
            float ls = 0.f;
            #pragma unroll
            for (int j = 0; j < BKV; j++) {
                float p = __expf(Ss[tid][j] - mn);
                Ss[tid][j] = p;
                ls += p;
            }
            m_s[tid] = mn;
            l_s[tid] = l_s[tid] * al + ls;
            a_s[tid] = al;
        }
        __syncthreads();

        // rescale O and accumulate P @ V (out cols tx*4..+3)
        float al[4];
        #pragma unroll
        for (int r = 0; r < 4; r++) al[r] = a_s[ty*4+r];
        #pragma unroll
        for (int r = 0; r < 4; r++)
            #pragma unroll
            for (int c = 0; c < 4; c++) o[r][c] *= al[r];

        #pragma unroll 8
        for (int j = 0; j < BKV; j++) {
            float p0 = Ss[ty*4+0][j], p1 = Ss[ty*4+1][j];
            float p2 = Ss[ty*4+2][j], p3 = Ss[ty*4+3][j];
            float v0 = Vs[j][tx*4+0], v1 = Vs[j][tx*4+1];
            float v2 = Vs[j][tx*4+2], v3 = Vs[j][tx*4+3];
            o[0][0]+=p0*v0; o[0][1]+=p0*v1; o[0][2]+=p0*v2; o[0][3]+=p0*v3;
            o[1][0]+=p1*v0; o[1][1]+=p1*v1; o[1][2]+=p1*v2; o[1][3]+=p1*v3;
            o[2][0]+=p2*v0; o[2][1]+=p2*v1; o[2][2]+=p2*v2; o[2][3]+=p2*v3;
            o[3][0]+=p3*v0; o[3][1]+=p3*v1; o[3][2]+=p3*v2; o[3][3]+=p3*v3;
        }
        __syncthreads();
    }

    // write ctx
    #pragma unroll
    for (int r = 0; r < 4; r++) {
        int qrow = qb * BQ + ty * 4 + r;
        float inv = 1.f / l_s[ty*4+r];
        float* op = O + base + (long)qrow * D_MODEL + tx * 4;
        op[0] = o[r][0] * inv;
        op[1] = o[r][1] * inv;
        op[2] = o[r][2] * inv;
        op[3] = o[r][3] * inv;
    }
}

// ---------------------------------------------------------------------------
// Host launcher
// ---------------------------------------------------------------------------
extern "C" void kernel_launch(void* const* d_in, const int* in_sizes, int n_in,
                              void* d_out, int out_size)
{
    const float* x     = (const float*)d_in[0];
    const float* ln1_w = (const float*)d_in[1];
    const float* ln1_b = (const float*)d_in[2];
    const float* Wq    = (const float*)d_in[3];
    const float* bq    = (const float*)d_in[4];
    const float* Wk    = (const float*)d_in[5];
    const float* bk    = (const float*)d_in[6];
    const float* Wv    = (const float*)d_in[7];
    const float* bv    = (const float*)d_in[8];
    const float* Wo    = (const float*)d_in[9];
    const float* bo    = (const float*)d_in[10];
    const float* ln2_w = (const float*)d_in[11];
    const float* ln2_b = (const float*)d_in[12];
    const float* W1    = (const float*)d_in[13];
    const float* b1    = (const float*)d_in[14];
    const float* W2    = (const float*)d_in[15];
    const float* b2    = (const float*)d_in[16];
    float* out = (float*)d_out;

    float *p_h, *p_q, *p_k, *p_v, *p_ctx, *p_x1, *p_h2, *p_ff;
    cudaGetSymbolAddress((void**)&p_h,   g_h);
    cudaGetSymbolAddress((void**)&p_q,   g_q);
    cudaGetSymbolAddress((void**)&p_k,   g_k);
    cudaGetSymbolAddress((void**)&p_v,   g_v);
    cudaGetSymbolAddress((void**)&p_ctx, g_ctx);
    cudaGetSymbolAddress((void**)&p_x1,  g_x1);
    cudaGetSymbolAddress((void**)&p_h2,  g_h2);
    cudaGetSymbolAddress((void**)&p_ff,  g_ff);

    // 1. h = LN1(x)
    layernorm_kernel<<<M_ROWS, 256>>>(x, ln1_w, ln1_b, p_h);

    // 2. q/k/v projections
    {
        dim3 grid(D_MODEL / 128, M_ROWS / 128);
        sgemm_kernel<false, false><<<grid, 256>>>(p_h, Wq, bq, nullptr, p_q, M_ROWS, D_MODEL, D_MODEL);
        sgemm_kernel<false, false><<<grid, 256>>>(p_h, Wk, bk, nullptr, p_k, M_ROWS, D_MODEL, D_MODEL);
        sgemm_kernel<false, false><<<grid, 256>>>(p_h, Wv, bv, nullptr, p_v, M_ROWS, D_MODEL, D_MODEL);
    }

    // 3. attention -> ctx
    {
        dim3 grid(S_ / 64, N_HEADS, B_);
        attn_kernel<<<grid, 256>>>(p_q, p_k, p_v, p_ctx);
    }

    // 4. x1 = x + ctx @ Wo + bo
    {
        dim3 grid(D_MODEL / 128, M_ROWS / 128);
        sgemm_kernel<false, true><<<grid, 256>>>(p_ctx, Wo, bo, x, p_x1, M_ROWS, D_MODEL, D_MODEL);
    }

    // 5. h2 = LN2(x1)
    layernorm_kernel<<<M_ROWS, 256>>>(p_x1, ln2_w, ln2_b, p_h2);

    // 6. ff = relu(h2 @ W1 + b1)
    {
        dim3 grid(D_FF / 128, M_ROWS / 128);
        sgemm_kernel<true, false><<<grid, 256>>>(p_h2, W1, b1, nullptr, p_ff, M_ROWS, D_FF, D_MODEL);
    }

    // 7. out = x1 + ff @ W2 + b2
    {
        dim3 grid(D_MODEL / 128, M_ROWS / 128);
        sgemm_kernel<false, true><<<grid, 256>>>(p_ff, W2, b2, p_x1, out, M_ROWS, D_MODEL, D_FF);
    }
}

// round 8
// speedup vs baseline: 1.6580x; 1.6580x over previous
#include <cuda_runtime.h>
#include <cstdint>

// ---------------------------------------------------------------------------
// TransformerBlock: B=2, S=2048, D=1024, H=16, Dk=64, Dff=4096, fp32
// Round 7 (resubmit of R2 — five infra timeouts, never measured):
// dense GEMMs on mma.sync.m16n8k8 TF32 (baseline-PTX tensor cores;
// tcgen05 unavailable — harness targets compute_103 without the 'a' feature).
// ---------------------------------------------------------------------------

#define D_MODEL 1024
#define N_HEADS 16
#define D_K     64
#define D_FF    4096
#define B_      2
#define S_      2048
#define M_ROWS  (B_ * S_)          // 4096

// ---------------- scratch (device globals; no allocations allowed) ----------
__device__ float g_h  [M_ROWS * D_MODEL];
__device__ float g_q  [M_ROWS * D_MODEL];
__device__ float g_k  [M_ROWS * D_MODEL];
__device__ float g_v  [M_ROWS * D_MODEL];
__device__ float g_ctx[M_ROWS * D_MODEL];
__device__ float g_x1 [M_ROWS * D_MODEL];
__device__ float g_h2 [M_ROWS * D_MODEL];
__device__ float g_ff [M_ROWS * D_FF];
// transposed (and tf32-rounded) weights: Wt[n][k] = rna(W[k][n])
__device__ float g_wqt[D_MODEL * D_MODEL];
__device__ float g_wkt[D_MODEL * D_MODEL];
__device__ float g_wvt[D_MODEL * D_MODEL];
__device__ float g_wot[D_MODEL * D_MODEL];
__device__ float g_w1t[D_FF * D_MODEL];
__device__ float g_w2t[D_MODEL * D_FF];

__device__ __forceinline__ float tf32_rna(float x) {
    uint32_t u;
    asm("cvt.rna.tf32.f32 %0, %1;" : "=r"(u) : "f"(x));
    return __uint_as_float(u);
}

__device__ __forceinline__ void mma_tf32(float c[4], const uint32_t a[4],
                                         const uint32_t b[2]) {
    asm volatile(
        "mma.sync.aligned.m16n8k8.row.col.f32.tf32.tf32.f32 "
        "{%0,%1,%2,%3}, {%4,%5,%6,%7}, {%8,%9}, {%0,%1,%2,%3};"
        : "+f"(c[0]), "+f"(c[1]), "+f"(c[2]), "+f"(c[3])
        : "r"(a[0]), "r"(a[1]), "r"(a[2]), "r"(a[3]), "r"(b[0]), "r"(b[1]));
}

// ---------------------------------------------------------------------------
// Fused transpose + tf32-round: Wt[n][k] = rna(W[k][n]),  W is [K,N] row-major
// ---------------------------------------------------------------------------
__global__ __launch_bounds__(256) void transpose_rna_kernel(
    const float* __restrict__ W, float* __restrict__ Wt, int K, int N)
{
    __shared__ float t[32][33];
    int n0 = blockIdx.x * 32, k0 = blockIdx.y * 32;
    int tx = threadIdx.x & 31, ty = threadIdx.x >> 5;  // 32 x 8
    #pragma unroll
    for (int i = 0; i < 4; i++)
        t[ty + 8 * i][tx] = W[(size_t)(k0 + ty + 8 * i) * N + n0 + tx];
    __syncthreads();
    #pragma unroll
    for (int i = 0; i < 4; i++)
        Wt[(size_t)(n0 + ty + 8 * i) * K + k0 + tx] = tf32_rna(t[tx][ty + 8 * i]);
}

// ---------------------------------------------------------------------------
// TF32 tensor-core GEMM: C[M,N] = A[M,K] @ Wt[N,K]^T + bias (+res) (+relu)
// 128x128/CTA, 8 warps (2x4), warp tile 64x32, BK=16, double-buffered smem.
// A and Wt values must already be tf32-rounded (done at producers).
// ---------------------------------------------------------------------------
#define SPAD 20

template<bool RELU, bool RES, bool RNA>
__global__ __launch_bounds__(256, 2) void mgemm_kernel(
    const float* __restrict__ A, const float* __restrict__ Wt,
    const float* __restrict__ bias, const float* __restrict__ res,
    float* __restrict__ C, int M, int N, int K)
{
    __shared__ float As[2][128][SPAD];
    __shared__ float Bs[2][128][SPAD];

    const int tid = threadIdx.x, lane = tid & 31, wid = tid >> 5;
    const int warpM = wid & 1, warpN = wid >> 1;     // 2 x 4
    const int g = lane >> 2, t = lane & 3;
    const int m0 = blockIdx.y * 128, n0 = blockIdx.x * 128;

    const int lrow = tid >> 1;            // 0..127
    const int lcg  = (tid & 1) * 8;       // 0 or 8

    float c[4][4][4];
    #pragma unroll
    for (int i = 0; i < 4; i++)
        #pragma unroll
        for (int j = 0; j < 4; j++)
            #pragma unroll
            for (int r = 0; r < 4; r++) c[i][j][r] = 0.f;

    const float* Ag = A  + (size_t)(m0 + lrow) * K + lcg;
    const float* Bg = Wt + (size_t)(n0 + lrow) * K + lcg;

    // prologue: stage 0
    {
        float4 a0v = *(const float4*)(Ag);
        float4 a1v = *(const float4*)(Ag + 4);
        float4 b0v = *(const float4*)(Bg);
        float4 b1v = *(const float4*)(Bg + 4);
        *(float4*)&As[0][lrow][lcg]     = a0v;
        *(float4*)&As[0][lrow][lcg + 4] = a1v;
        *(float4*)&Bs[0][lrow][lcg]     = b0v;
        *(float4*)&Bs[0][lrow][lcg + 4] = b1v;
    }
    __syncthreads();

    const int nit = K >> 4;
    for (int it = 0; it < nit; ++it) {
        const int buf = it & 1;
        float4 pa0, pa1, pb0, pb1;
        const bool more = (it + 1 < nit);
        if (more) {
            const float* Ap = Ag + (it + 1) * 16;
            const float* Bp = Bg + (it + 1) * 16;
            pa0 = *(const float4*)(Ap);
            pa1 = *(const float4*)(Ap + 4);
            pb0 = *(const float4*)(Bp);
            pb1 = *(const float4*)(Bp + 4);
        }

        #pragma unroll
        for (int kk = 0; kk < 16; kk += 8) {
            uint32_t a[4][4], b[4][2];
            #pragma unroll
            for (int mt = 0; mt < 4; mt++) {
                int row = warpM * 64 + mt * 16 + g;
                a[mt][0] = __float_as_uint(As[buf][row]    [kk + t]);
                a[mt][1] = __float_as_uint(As[buf][row + 8][kk + t]);
                a[mt][2] = __float_as_uint(As[buf][row]    [kk + t + 4]);
                a[mt][3] = __float_as_uint(As[buf][row + 8][kk + t + 4]);
            }
            #pragma unroll
            for (int nt = 0; nt < 4; nt++) {
                int n = warpN * 32 + nt * 8 + g;
                b[nt][0] = __float_as_uint(Bs[buf][n][kk + t]);
                b[nt][1] = __float_as_uint(Bs[buf][n][kk + t + 4]);
            }
            #pragma unroll
            for (int mt = 0; mt < 4; mt++)
                #pragma unroll
                for (int nt = 0; nt < 4; nt++)
                    mma_tf32(c[mt][nt], a[mt], b[nt]);
        }

        if (more) {
            int nb = buf ^ 1;
            *(float4*)&As[nb][lrow][lcg]     = pa0;
            *(float4*)&As[nb][lrow][lcg + 4] = pa1;
            *(float4*)&Bs[nb][lrow][lcg]     = pb0;
            *(float4*)&Bs[nb][lrow][lcg + 4] = pb1;
        }
        __syncthreads();
    }

    // epilogue
    #pragma unroll
    for (int mt = 0; mt < 4; mt++) {
        #pragma unroll
        for (int nt = 0; nt < 4; nt++) {
            int row = m0 + warpM * 64 + mt * 16 + g;
            int col = n0 + warpN * 32 + nt * 8 + t * 2;
            float b0 = bias[col], b1 = bias[col + 1];
            float v00 = c[mt][nt][0] + b0, v01 = c[mt][nt][1] + b1;
            float v10 = c[mt][nt][2] + b0, v11 = c[mt][nt][3] + b1;
            if (RES) {
                float2 r0 = *(const float2*)(res + (size_t)row * N + col);
                float2 r1 = *(const float2*)(res + (size_t)(row + 8) * N + col);
                v00 += r0.x; v01 += r0.y; v10 += r1.x; v11 += r1.y;
            }
            if (RELU) {
                v00 = fmaxf(v00, 0.f); v01 = fmaxf(v01, 0.f);
                v10 = fmaxf(v10, 0.f); v11 = fmaxf(v11, 0.f);
            }
            if (RNA) {
                v00 = tf32_rna(v00); v01 = tf32_rna(v01);
                v10 = tf32_rna(v10); v11 = tf32_rna(v11);
            }
            float2 o0 = make_float2(v00, v01);
            float2 o1 = make_float2(v10, v11);
            *(float2*)(C + (size_t)row * N + col)       = o0;
            *(float2*)(C + (size_t)(row + 8) * N + col) = o1;
        }
    }
}

// ---------------------------------------------------------------------------
// LayerNorm: one block per row; output tf32-rounded (feeds GEMMs only)
// ---------------------------------------------------------------------------
__global__ __launch_bounds__(256) void layernorm_kernel(
    const float* __restrict__ x, const float* __restrict__ w,
    const float* __restrict__ b, float* __restrict__ out)
{
    int row = blockIdx.x;
    const float* xr = x + (long)row * D_MODEL;
    int c = threadIdx.x * 4;
    float4 v = *(const float4*)(xr + c);
    float s  = v.x + v.y + v.z + v.w;
    float ss = v.x*v.x + v.y*v.y + v.z*v.z + v.w*v.w;

    #pragma unroll
    for (int o = 16; o > 0; o >>= 1) {
        s  += __shfl_xor_sync(0xffffffffu, s,  o);
        ss += __shfl_xor_sync(0xffffffffu, ss, o);
    }
    __shared__ float rs[8], rss[8];
    int wid = threadIdx.x >> 5, lane = threadIdx.x & 31;
    if (lane == 0) { rs[wid] = s; rss[wid] = ss; }
    __syncthreads();
    s = 0.f; ss = 0.f;
    #pragma unroll
    for (int i = 0; i < 8; i++) { s += rs[i]; ss += rss[i]; }

    float mu  = s * (1.0f / D_MODEL);
    float var = ss * (1.0f / D_MODEL) - mu * mu;
    float rstd = rsqrtf(var + 1e-5f);

    float4 wv = *(const float4*)(w + c);
    float4 bv = *(const float4*)(b + c);
    float4 o4;
    o4.x = tf32_rna((v.x - mu) * rstd * wv.x + bv.x);
    o4.y = tf32_rna((v.y - mu) * rstd * wv.y + bv.y);
    o4.z = tf32_rna((v.z - mu) * rstd * wv.z + bv.z);
    o4.w = tf32_rna((v.w - mu) * rstd * wv.w + bv.w);
    *(float4*)(out + (long)row * D_MODEL + c) = o4;
}

// ---------------------------------------------------------------------------
// Flash attention: BQ=64, BKV=32, online softmax; ctx output tf32-rounded
// ---------------------------------------------------------------------------
__global__ __launch_bounds__(256) void attn_kernel(
    const float* __restrict__ Q, const float* __restrict__ K,
    const float* __restrict__ V, float* __restrict__ O)
{
    const int BQ = 64, BKV = 32;
    __shared__ float Qs[BQ][D_K + 1];
    __shared__ float Ks[BKV][D_K + 1];
    __shared__ float Vs[BKV][D_K + 1];
    __shared__ float Ss[BQ][BKV + 1];
    __shared__ float m_s[BQ], l_s[BQ], a_s[BQ];

    int qb = blockIdx.x, h = blockIdx.y, b = blockIdx.z;
    int tid = threadIdx.x;
    int tx = tid & 15, ty = tid >> 4;
    const float scale = 0.125f;

    long base = ((long)b * S_) * D_MODEL + h * D_K;

    {
        int i  = tid >> 2;
        int c4 = (tid & 3) * 4;
        const float* qp = Q + base + (long)(qb * BQ + i) * D_MODEL;
        #pragma unroll
        for (int u = 0; u < 4; u++) {
            float4 vv = *(const float4*)(qp + c4 + u * 16);
            Qs[i][c4 + u * 16 + 0] = vv.x;
            Qs[i][c4 + u * 16 + 1] = vv.y;
            Qs[i][c4 + u * 16 + 2] = vv.z;
            Qs[i][c4 + u * 16 + 3] = vv.w;
        }
    }
    if (tid < BQ) { m_s[tid] = -1e30f; l_s[tid] = 0.f; }

    float o[4][4];
    #pragma unroll
    for (int r = 0; r < 4; r++)
        #pragma unroll
        for (int c = 0; c < 4; c++) o[r][c] = 0.f;

    __syncthreads();

    for (int j0 = 0; j0 < S_; j0 += BKV) {
        {
            int row = tid >> 3;
            int c0  = (tid & 7) * 8;
            const float* kp = K + base + (long)(j0 + row) * D_MODEL;
            const float* vp = V + base + (long)(j0 + row) * D_MODEL;
            float4 k1 = *(const float4*)(kp + c0);
            float4 k2 = *(const float4*)(kp + c0 + 4);
            float4 v1 = *(const float4*)(vp + c0);
            float4 v2 = *(const float4*)(vp + c0 + 4);
            Ks[row][c0+0]=k1.x; Ks[row][c0+1]=k1.y; Ks[row][c0+2]=k1.z; Ks[row][c0+3]=k1.w;
            Ks[row][c0+4]=k2.x; Ks[row][c0+5]=k2.y; Ks[row][c0+6]=k2.z; Ks[row][c0+7]=k2.w;
            Vs[row][c0+0]=v1.x; Vs[row][c0+1]=v1.y; Vs[row][c0+2]=v1.z; Vs[row][c0+3]=v1.w;
            Vs[row][c0+4]=v2.x; Vs[row][c0+5]=v2.y; Vs[row][c0+6]=v2.z; Vs[row][c0+7]=v2.w;
        }
        __syncthreads();

        float acc[4][2];
        #pragma unroll
        for (int r = 0; r < 4; r++) { acc[r][0] = 0.f; acc[r][1] = 0.f; }
        #pragma unroll 8
        for (int d = 0; d < D_K; d++) {
            float a0 = Qs[ty*4+0][d], a1 = Qs[ty*4+1][d];
            float a2 = Qs[ty*4+2][d], a3 = Qs[ty*4+3][d];
            float b0 = Ks[tx*2+0][d], b1 = Ks[tx*2+1][d];
            acc[0][0] += a0*b0; acc[0][1] += a0*b1;
            acc[1][0] += a1*b0; acc[1][1] += a1*b1;
            acc[2][0] += a2*b0; acc[2][1] += a2*b1;
            acc[3][0] += a3*b0; acc[3][1] += a3*b1;
        }
        #pragma unroll
        for (int r = 0; r < 4; r++) {
            Ss[ty*4+r][tx*2+0] = acc[r][0] * scale;
            Ss[ty*4+r][tx*2+1] = acc[r][1] * scale;
        }
        __syncthreads();

        if (tid < BQ) {
            float mo = m_s[tid], mn = mo;
            #pragma unroll
            for (int j = 0; j < BKV; j++) mn = fmaxf(mn, Ss[tid][j]);
            float al = __expf(mo - mn);
            float ls = 0.f;
            #pragma unroll
            for (int j = 0; j < BKV; j++) {
                float p = __expf(Ss[tid][j] - mn);
                Ss[tid][j] = p;
                ls += p;
            }
            m_s[tid] = mn;
            l_s[tid] = l_s[tid] * al + ls;
            a_s[tid] = al;
        }
        __syncthreads();

        float al[4];
        #pragma unroll
        for (int r = 0; r < 4; r++) al[r] = a_s[ty*4+r];
        #pragma unroll
        for (int r = 0; r < 4; r++)
            #pragma unroll
            for (int c = 0; c < 4; c++) o[r][c] *= al[r];

        #pragma unroll 8
        for (int j = 0; j < BKV; j++) {
            float p0 = Ss[ty*4+0][j], p1 = Ss[ty*4+1][j];
            float p2 = Ss[ty*4+2][j], p3 = Ss[ty*4+3][j];
            float v0 = Vs[j][tx*4+0], v1 = Vs[j][tx*4+1];
            float v2 = Vs[j][tx*4+2], v3 = Vs[j][tx*4+3];
            o[0][0]+=p0*v0; o[0][1]+=p0*v1; o[0][2]+=p0*v2; o[0][3]+=p0*v3;
            o[1][0]+=p1*v0; o[1][1]+=p1*v1; o[1][2]+=p1*v2; o[1][3]+=p1*v3;
            o[2][0]+=p2*v0; o[2][1]+=p2*v1; o[2][2]+=p2*v2; o[2][3]+=p2*v3;
            o[3][0]+=p3*v0; o[3][1]+=p3*v1; o[3][2]+=p3*v2; o[3][3]+=p3*v3;
        }
        __syncthreads();
    }

    #pragma unroll
    for (int r = 0; r < 4; r++) {
        int qrow = qb * BQ + ty * 4 + r;
        float inv = 1.f / l_s[ty*4+r];
        float* op = O + base + (long)qrow * D_MODEL + tx * 4;
        op[0] = tf32_rna(o[r][0] * inv);
        op[1] = tf32_rna(o[r][1] * inv);
        op[2] = tf32_rna(o[r][2] * inv);
        op[3] = tf32_rna(o[r][3] * inv);
    }
}

// ---------------------------------------------------------------------------
// Host launcher
// ---------------------------------------------------------------------------
extern "C" void kernel_launch(void* const* d_in, const int* in_sizes, int n_in,
                              void* d_out, int out_size)
{
    const float* x     = (const float*)d_in[0];
    const float* ln1_w = (const float*)d_in[1];
    const float* ln1_b = (const float*)d_in[2];
    const float* Wq    = (const float*)d_in[3];
    const float* bq    = (const float*)d_in[4];
    const float* Wk    = (const float*)d_in[5];
    const float* bk    = (const float*)d_in[6];
    const float* Wv    = (const float*)d_in[7];
    const float* bv    = (const float*)d_in[8];
    const float* Wo    = (const float*)d_in[9];
    const float* bo    = (const float*)d_in[10];
    const float* ln2_w = (const float*)d_in[11];
    const float* ln2_b = (const float*)d_in[12];
    const float* W1    = (const float*)d_in[13];
    const float* b1    = (const float*)d_in[14];
    const float* W2    = (const float*)d_in[15];
    const float* b2    = (const float*)d_in[16];
    float* out = (float*)d_out;

    float *p_h, *p_q, *p_k, *p_v, *p_ctx, *p_x1, *p_h2, *p_ff;
    float *p_wqt, *p_wkt, *p_wvt, *p_wot, *p_w1t, *p_w2t;
    cudaGetSymbolAddress((void**)&p_h,   g_h);
    cudaGetSymbolAddress((void**)&p_q,   g_q);
    cudaGetSymbolAddress((void**)&p_k,   g_k);
    cudaGetSymbolAddress((void**)&p_v,   g_v);
    cudaGetSymbolAddress((void**)&p_ctx, g_ctx);
    cudaGetSymbolAddress((void**)&p_x1,  g_x1);
    cudaGetSymbolAddress((void**)&p_h2,  g_h2);
    cudaGetSymbolAddress((void**)&p_ff,  g_ff);
    cudaGetSymbolAddress((void**)&p_wqt, g_wqt);
    cudaGetSymbolAddress((void**)&p_wkt, g_wkt);
    cudaGetSymbolAddress((void**)&p_wvt, g_wvt);
    cudaGetSymbolAddress((void**)&p_wot, g_wot);
    cudaGetSymbolAddress((void**)&p_w1t, g_w1t);
    cudaGetSymbolAddress((void**)&p_w2t, g_w2t);

    // weight transposes (+ tf32 rounding)
    transpose_rna_kernel<<<dim3(D_MODEL/32, D_MODEL/32), 256>>>(Wq, p_wqt, D_MODEL, D_MODEL);
    transpose_rna_kernel<<<dim3(D_MODEL/32, D_MODEL/32), 256>>>(Wk, p_wkt, D_MODEL, D_MODEL);
    transpose_rna_kernel<<<dim3(D_MODEL/32, D_MODEL/32), 256>>>(Wv, p_wvt, D_MODEL, D_MODEL);
    transpose_rna_kernel<<<dim3(D_MODEL/32, D_MODEL/32), 256>>>(Wo, p_wot, D_MODEL, D_MODEL);
    transpose_rna_kernel<<<dim3(D_FF/32,    D_MODEL/32), 256>>>(W1, p_w1t, D_MODEL, D_FF);
    transpose_rna_kernel<<<dim3(D_MODEL/32, D_FF/32),    256>>>(W2, p_w2t, D_FF,    D_MODEL);

    // 1. h = LN1(x)  (tf32-rounded output)
    layernorm_kernel<<<M_ROWS, 256>>>(x, ln1_w, ln1_b, p_h);

    // 2. q/k/v projections (tensor cores)
    {
        dim3 grid(D_MODEL / 128, M_ROWS / 128);
        mgemm_kernel<false, false, false><<<grid, 256>>>(p_h, p_wqt, bq, nullptr, p_q, M_ROWS, D_MODEL, D_MODEL);
        mgemm_kernel<false, false, false><<<grid, 256>>>(p_h, p_wkt, bk, nullptr, p_k, M_ROWS, D_MODEL, D_MODEL);
        mgemm_kernel<false, false, false><<<grid, 256>>>(p_h, p_wvt, bv, nullptr, p_v, M_ROWS, D_MODEL, D_MODEL);
    }

    // 3. attention -> ctx (tf32-rounded output)
    {
        dim3 grid(S_ / 64, N_HEADS, B_);
        attn_kernel<<<grid, 256>>>(p_q, p_k, p_v, p_ctx);
    }

    // 4. x1 = x + ctx @ Wo + bo
    {
        dim3 grid(D_MODEL / 128, M_ROWS / 128);
        mgemm_kernel<false, true, false><<<grid, 256>>>(p_ctx, p_wot, bo, x, p_x1, M_ROWS, D_MODEL, D_MODEL);
    }

    // 5. h2 = LN2(x1)  (tf32-rounded output)
    layernorm_kernel<<<M_ROWS, 256>>>(p_x1, ln2_w, ln2_b, p_h2);

    // 6. ff = relu(h2 @ W1 + b1)  (tf32-rounded output; feeds FFN2)
    {
        dim3 grid(D_FF / 128, M_ROWS / 128);
        mgemm_kernel<true, false, true><<<grid, 256>>>(p_h2, p_w1t, b1, nullptr, p_ff, M_ROWS, D_FF, D_MODEL);
    }

    // 7. out = x1 + ff @ W2 + b2
    {
        dim3 grid(D_MODEL / 128, M_ROWS / 128);
        mgemm_kernel<false, true, false><<<grid, 256>>>(p_ff, p_w2t, b2, p_x1, out, M_ROWS, D_MODEL, D_FF);
    }
}

// round 11
// speedup vs baseline: 2.2035x; 1.3290x over previous
#include <cuda_runtime.h>
#include <cstdint>

// ---------------------------------------------------------------------------
// TransformerBlock: B=2, S=2048, D=1024, H=16, Dk=64, Dff=4096, fp32
// Round 11 (resubmit of R9 — two infra timeouts, never measured):
// R8 verified GEMMs on mma.sync tf32 (2339us). Attention moves to the same
// verified m16n8k8 tf32 fragment paths: BQ=64,BKV=64, mma QK^T and PV,
// parallel softmax (4 threads/row), O accum in registers.
// ---------------------------------------------------------------------------

#define D_MODEL 1024
#define N_HEADS 16
#define D_K     64
#define D_FF    4096
#define B_      2
#define S_      2048
#define M_ROWS  (B_ * S_)          // 4096

// ---------------- scratch (device globals; no allocations allowed) ----------
__device__ float g_h  [M_ROWS * D_MODEL];
__device__ float g_q  [M_ROWS * D_MODEL];
__device__ float g_k  [M_ROWS * D_MODEL];
__device__ float g_v  [M_ROWS * D_MODEL];
__device__ float g_ctx[M_ROWS * D_MODEL];
__device__ float g_x1 [M_ROWS * D_MODEL];
__device__ float g_h2 [M_ROWS * D_MODEL];
__device__ float g_ff [M_ROWS * D_FF];
// transposed (and tf32-rounded) weights: Wt[n][k] = rna(W[k][n])
__device__ float g_wqt[D_MODEL * D_MODEL];
__device__ float g_wkt[D_MODEL * D_MODEL];
__device__ float g_wvt[D_MODEL * D_MODEL];
__device__ float g_wot[D_MODEL * D_MODEL];
__device__ float g_w1t[D_FF * D_MODEL];
__device__ float g_w2t[D_MODEL * D_FF];

__device__ __forceinline__ float tf32_rna(float x) {
    uint32_t u;
    asm("cvt.rna.tf32.f32 %0, %1;" : "=r"(u) : "f"(x));
    return __uint_as_float(u);
}

__device__ __forceinline__ void mma_tf32(float c[4], const uint32_t a[4],
                                         const uint32_t b[2]) {
    asm volatile(
        "mma.sync.aligned.m16n8k8.row.col.f32.tf32.tf32.f32 "
        "{%0,%1,%2,%3}, {%4,%5,%6,%7}, {%8,%9}, {%0,%1,%2,%3};"
        : "+f"(c[0]), "+f"(c[1]), "+f"(c[2]), "+f"(c[3])
        : "r"(a[0]), "r"(a[1]), "r"(a[2]), "r"(a[3]), "r"(b[0]), "r"(b[1]));
}

// ---------------------------------------------------------------------------
// Fused transpose + tf32-round: Wt[n][k] = rna(W[k][n]),  W is [K,N] row-major
// ---------------------------------------------------------------------------
__global__ __launch_bounds__(256) void transpose_rna_kernel(
    const float* __restrict__ W, float* __restrict__ Wt, int K, int N)
{
    __shared__ float t[32][33];
    int n0 = blockIdx.x * 32, k0 = blockIdx.y * 32;
    int tx = threadIdx.x & 31, ty = threadIdx.x >> 5;  // 32 x 8
    #pragma unroll
    for (int i = 0; i < 4; i++)
        t[ty + 8 * i][tx] = W[(size_t)(k0 + ty + 8 * i) * N + n0 + tx];
    __syncthreads();
    #pragma unroll
    for (int i = 0; i < 4; i++)
        Wt[(size_t)(n0 + ty + 8 * i) * K + k0 + tx] = tf32_rna(t[tx][ty + 8 * i]);
}

// ---------------------------------------------------------------------------
// TF32 tensor-core GEMM: C[M,N] = A[M,K] @ Wt[N,K]^T + bias (+res) (+relu)
// 128x128/CTA, 8 warps (2x4), warp tile 64x32, BK=16, double-buffered smem.
// (verified R8: 2339us total, rel_err 2.1e-4)
// ---------------------------------------------------------------------------
#define SPAD 20

template<bool RELU, bool RES, bool RNA>
__global__ __launch_bounds__(256, 2) void mgemm_kernel(
    const float* __restrict__ A, const float* __restrict__ Wt,
    const float* __restrict__ bias, const float* __restrict__ res,
    float* __restrict__ C, int M, int N, int K)
{
    __shared__ float As[2][128][SPAD];
    __shared__ float Bs[2][128][SPAD];

    const int tid = threadIdx.x, lane = tid & 31, wid = tid >> 5;
    const int warpM = wid & 1, warpN = wid >> 1;     // 2 x 4
    const int g = lane >> 2, t = lane & 3;
    const int m0 = blockIdx.y * 128, n0 = blockIdx.x * 128;

    const int lrow = tid >> 1;            // 0..127
    const int lcg  = (tid & 1) * 8;       // 0 or 8

    float c[4][4][4];
    #pragma unroll
    for (int i = 0; i < 4; i++)
        #pragma unroll
        for (int j = 0; j < 4; j++)
            #pragma unroll
            for (int r = 0; r < 4; r++) c[i][j][r] = 0.f;

    const float* Ag = A  + (size_t)(m0 + lrow) * K + lcg;
    const float* Bg = Wt + (size_t)(n0 + lrow) * K + lcg;

    // prologue: stage 0
    {
        float4 a0v = *(const float4*)(Ag);
        float4 a1v = *(const float4*)(Ag + 4);
        float4 b0v = *(const float4*)(Bg);
        float4 b1v = *(const float4*)(Bg + 4);
        *(float4*)&As[0][lrow][lcg]     = a0v;
        *(float4*)&As[0][lrow][lcg + 4] = a1v;
        *(float4*)&Bs[0][lrow][lcg]     = b0v;
        *(float4*)&Bs[0][lrow][lcg + 4] = b1v;
    }
    __syncthreads();

    const int nit = K >> 4;
    for (int it = 0; it < nit; ++it) {
        const int buf = it & 1;
        float4 pa0, pa1, pb0, pb1;
        const bool more = (it + 1 < nit);
        if (more) {
            const float* Ap = Ag + (it + 1) * 16;
            const float* Bp = Bg + (it + 1) * 16;
            pa0 = *(const float4*)(Ap);
            pa1 = *(const float4*)(Ap + 4);
            pb0 = *(const float4*)(Bp);
            pb1 = *(const float4*)(Bp + 4);
        }

        #pragma unroll
        for (int kk = 0; kk < 16; kk += 8) {
            uint32_t a[4][4], b[4][2];
            #pragma unroll
            for (int mt = 0; mt < 4; mt++) {
                int row = warpM * 64 + mt * 16 + g;
                a[mt][0] = __float_as_uint(As[buf][row]    [kk + t]);
                a[mt][1] = __float_as_uint(As[buf][row + 8][kk + t]);
                a[mt][2] = __float_as_uint(As[buf][row]    [kk + t + 4]);
                a[mt][3] = __float_as_uint(As[buf][row + 8][kk + t + 4]);
            }
            #pragma unroll
            for (int nt = 0; nt < 4; nt++) {
                int n = warpN * 32 + nt * 8 + g;
                b[nt][0] = __float_as_uint(Bs[buf][n][kk + t]);
                b[nt][1] = __float_as_uint(Bs[buf][n][kk + t + 4]);
            }
            #pragma unroll
            for (int mt = 0; mt < 4; mt++)
                #pragma unroll
                for (int nt = 0; nt < 4; nt++)
                    mma_tf32(c[mt][nt], a[mt], b[nt]);
        }

        if (more) {
            int nb = buf ^ 1;
            *(float4*)&As[nb][lrow][lcg]     = pa0;
            *(float4*)&As[nb][lrow][lcg + 4] = pa1;
            *(float4*)&Bs[nb][lrow][lcg]     = pb0;
            *(float4*)&Bs[nb][lrow][lcg + 4] = pb1;
        }
        __syncthreads();
    }

    // epilogue
    #pragma unroll
    for (int mt = 0; mt < 4; mt++) {
        #pragma unroll
        for (int nt = 0; nt < 4; nt++) {
            int row = m0 + warpM * 64 + mt * 16 + g;
            int col = n0 + warpN * 32 + nt * 8 + t * 2;
            float b0 = bias[col], b1 = bias[col + 1];
            float v00 = c[mt][nt][0] + b0, v01 = c[mt][nt][1] + b1;
            float v10 = c[mt][nt][2] + b0, v11 = c[mt][nt][3] + b1;
            if (RES) {
                float2 r0 = *(const float2*)(res + (size_t)row * N + col);
                float2 r1 = *(const float2*)(res + (size_t)(row + 8) * N + col);
                v00 += r0.x; v01 += r0.y; v10 += r1.x; v11 += r1.y;
            }
            if (RELU) {
                v00 = fmaxf(v00, 0.f); v01 = fmaxf(v01, 0.f);
                v10 = fmaxf(v10, 0.f); v11 = fmaxf(v11, 0.f);
            }
            if (RNA) {
                v00 = tf32_rna(v00); v01 = tf32_rna(v01);
                v10 = tf32_rna(v10); v11 = tf32_rna(v11);
            }
            float2 o0 = make_float2(v00, v01);
            float2 o1 = make_float2(v10, v11);
            *(float2*)(C + (size_t)row * N + col)       = o0;
            *(float2*)(C + (size_t)(row + 8) * N + col) = o1;
        }
    }
}

// ---------------------------------------------------------------------------
// LayerNorm: one block per row; output tf32-rounded (feeds GEMMs only)
// ---------------------------------------------------------------------------
__global__ __launch_bounds__(256) void layernorm_kernel(
    const float* __restrict__ x, const float* __restrict__ w,
    const float* __restrict__ b, float* __restrict__ out)
{
    int row = blockIdx.x;
    const float* xr = x + (long)row * D_MODEL;
    int c = threadIdx.x * 4;
    float4 v = *(const float4*)(xr + c);
    float s  = v.x + v.y + v.z + v.w;
    float ss = v.x*v.x + v.y*v.y + v.z*v.z + v.w*v.w;

    #pragma unroll
    for (int o = 16; o > 0; o >>= 1) {
        s  += __shfl_xor_sync(0xffffffffu, s,  o);
        ss += __shfl_xor_sync(0xffffffffu, ss, o);
    }
    __shared__ float rs[8], rss[8];
    int wid = threadIdx.x >> 5, lane = threadIdx.x & 31;
    if (lane == 0) { rs[wid] = s; rss[wid] = ss; }
    __syncthreads();
    s = 0.f; ss = 0.f;
    #pragma unroll
    for (int i = 0; i < 8; i++) { s += rs[i]; ss += rss[i]; }

    float mu  = s * (1.0f / D_MODEL);
    float var = ss * (1.0f / D_MODEL) - mu * mu;
    float rstd = rsqrtf(var + 1e-5f);

    float4 wv = *(const float4*)(w + c);
    float4 bv = *(const float4*)(b + c);
    float4 o4;
    o4.x = tf32_rna((v.x - mu) * rstd * wv.x + bv.x);
    o4.y = tf32_rna((v.y - mu) * rstd * wv.y + bv.y);
    o4.z = tf32_rna((v.z - mu) * rstd * wv.z + bv.z);
    o4.w = tf32_rna((v.w - mu) * rstd * wv.w + bv.w);
    *(float4*)(out + (long)row * D_MODEL + c) = o4;
}

// ---------------------------------------------------------------------------
// Tensor-core flash attention: BQ=64, BKV=64, mma.sync tf32 for QK^T and PV.
// 8 warps, warp tile 16x32 (warpM in 0..3, warpN in 0..1).
// Fragment index math identical to mgemm_kernel (hardware-verified R8).
// smem stride 68 floats keeps fragment gathers <=2-way conflicted.
// ---------------------------------------------------------------------------
#define AST 68
#define ATT_SMEM_BYTES (4 * 64 * AST * 4 + 3 * 64 * 4)   // 70400

__global__ __launch_bounds__(256) void attn_mma_kernel(
    const float* __restrict__ Q, const float* __restrict__ K,
    const float* __restrict__ V, float* __restrict__ O)
{
    extern __shared__ float sm[];
    float (*Qs)[AST] = (float(*)[AST])(sm);
    float (*Ks)[AST] = (float(*)[AST])(sm + 64 * AST);
    float (*Vs)[AST] = (float(*)[AST])(sm + 2 * 64 * AST);
    float (*Ss)[AST] = (float(*)[AST])(sm + 3 * 64 * AST);
    float* m_s = sm + 4 * 64 * AST;
    float* l_s = m_s + 64;
    float* a_s = l_s + 64;

    const int qb = blockIdx.x, h = blockIdx.y, b = blockIdx.z;
    const int tid = threadIdx.x, lane = tid & 31, wid = tid >> 5;
    const int warpM = wid >> 1, warpN = wid & 1;   // 4 x 2
    const int g = lane >> 2, t = lane & 3;
    const int r0 = warpM * 16 + g;                 // fragment row (and r0+8)
    const float scale = 0.125f;                    // 1/sqrt(64)

    const size_t base = ((size_t)b * S_) * D_MODEL + h * D_K;

    // load Q tile 64x64 (tf32-rounded)
    {
        int row = tid >> 2;
        int c0  = (tid & 3) * 16;
        const float* qp = Q + base + (size_t)(qb * 64 + row) * D_MODEL + c0;
        #pragma unroll
        for (int u = 0; u < 4; u++) {
            float4 v4 = *(const float4*)(qp + u * 4);
            Qs[row][c0 + u*4 + 0] = tf32_rna(v4.x);
            Qs[row][c0 + u*4 + 1] = tf32_rna(v4.y);
            Qs[row][c0 + u*4 + 2] = tf32_rna(v4.z);
            Qs[row][c0 + u*4 + 3] = tf32_rna(v4.w);
        }
    }
    if (tid < 64) { m_s[tid] = -1e30f; l_s[tid] = 0.f; }

    float oacc[4][4];
    #pragma unroll
    for (int nt = 0; nt < 4; nt++)
        #pragma unroll
        for (int i = 0; i < 4; i++) oacc[nt][i] = 0.f;

    __syncthreads();

    for (int j0 = 0; j0 < S_; j0 += 64) {
        // load K and V tiles 64x64 (tf32-rounded)
        {
            int row = tid >> 2;
            int c0  = (tid & 3) * 16;
            const float* kp = K + base + (size_t)(j0 + row) * D_MODEL + c0;
            const float* vp = V + base + (size_t)(j0 + row) * D_MODEL + c0;
            #pragma unroll
            for (int u = 0; u < 4; u++) {
                float4 k4 = *(const float4*)(kp + u * 4);
                float4 v4 = *(const float4*)(vp + u * 4);
                Ks[row][c0 + u*4 + 0] = tf32_rna(k4.x);
                Ks[row][c0 + u*4 + 1] = tf32_rna(k4.y);
                Ks[row][c0 + u*4 + 2] = tf32_rna(k4.z);
                Ks[row][c0 + u*4 + 3] = tf32_rna(k4.w);
                Vs[row][c0 + u*4 + 0] = tf32_rna(v4.x);
                Vs[row][c0 + u*4 + 1] = tf32_rna(v4.y);
                Vs[row][c0 + u*4 + 2] = tf32_rna(v4.z);
                Vs[row][c0 + u*4 + 3] = tf32_rna(v4.w);
            }
        }
        __syncthreads();

        // S = Q @ K^T  (warp tile 16x32)
        float sacc[4][4];
        #pragma unroll
        for (int nt = 0; nt < 4; nt++)
            #pragma unroll
            for (int i = 0; i < 4; i++) sacc[nt][i] = 0.f;

        #pragma unroll
        for (int kk = 0; kk < 64; kk += 8) {
            uint32_t a[4], bfr[4][2];
            a[0] = __float_as_uint(Qs[r0]    [kk + t]);
            a[1] = __float_as_uint(Qs[r0 + 8][kk + t]);
            a[2] = __float_as_uint(Qs[r0]    [kk + t + 4]);
            a[3] = __float_as_uint(Qs[r0 + 8][kk + t + 4]);
            #pragma unroll
            for (int nt = 0; nt < 4; nt++) {
                int n = warpN * 32 + nt * 8 + g;
                bfr[nt][0] = __float_as_uint(Ks[n][kk + t]);
                bfr[nt][1] = __float_as_uint(Ks[n][kk + t + 4]);
            }
            #pragma unroll
            for (int nt = 0; nt < 4; nt++)
                mma_tf32(sacc[nt], a, bfr[nt]);
        }
        #pragma unroll
        for (int nt = 0; nt < 4; nt++) {
            int col = warpN * 32 + nt * 8 + 2 * t;
            Ss[r0]    [col]     = sacc[nt][0] * scale;
            Ss[r0]    [col + 1] = sacc[nt][1] * scale;
            Ss[r0 + 8][col]     = sacc[nt][2] * scale;
            Ss[r0 + 8][col + 1] = sacc[nt][3] * scale;
        }
        __syncthreads();

        // online softmax: 4 threads per row, 16 cols each
        {
            int r = tid >> 2, sub = tid & 3;
            float mx = -1e30f;
            #pragma unroll
            for (int j = 0; j < 16; j++) mx = fmaxf(mx, Ss[r][sub * 16 + j]);
            mx = fmaxf(mx, __shfl_xor_sync(0xffffffffu, mx, 1));
            mx = fmaxf(mx, __shfl_xor_sync(0xffffffffu, mx, 2));
            float mo = m_s[r];
            float mn = fmaxf(mo, mx);
            float ls = 0.f;
            #pragma unroll
            for (int j = 0; j < 16; j++) {
                float p = __expf(Ss[r][sub * 16 + j] - mn);
                Ss[r][sub * 16 + j] = tf32_rna(p);
                ls += p;
            }
            ls += __shfl_xor_sync(0xffffffffu, ls, 1);
            ls += __shfl_xor_sync(0xffffffffu, ls, 2);
            if (sub == 0) {
                float al = __expf(mo - mn);
                m_s[r] = mn;
                l_s[r] = l_s[r] * al + ls;
                a_s[r] = al;
            }
        }
        __syncthreads();

        // rescale O and accumulate P @ V
        {
            float al0 = a_s[r0], al1 = a_s[r0 + 8];
            #pragma unroll
            for (int nt = 0; nt < 4; nt++) {
                oacc[nt][0] *= al0; oacc[nt][1] *= al0;
                oacc[nt][2] *= al1; oacc[nt][3] *= al1;
            }
        }
        #pragma unroll
        for (int kk = 0; kk < 64; kk += 8) {
            uint32_t a[4], bfr[4][2];
            a[0] = __float_as_uint(Ss[r0]    [kk + t]);
            a[1] = __float_as_uint(Ss[r0 + 8][kk + t]);
            a[2] = __float_as_uint(Ss[r0]    [kk + t + 4]);
            a[3] = __float_as_uint(Ss[r0 + 8][kk + t + 4]);
            #pragma unroll
            for (int nt = 0; nt < 4; nt++) {
                int n = warpN * 32 + nt * 8 + g;
                bfr[nt][0] = __float_as_uint(Vs[kk + t]    [n]);
                bfr[nt][1] = __float_as_uint(Vs[kk + t + 4][n]);
            }
            #pragma unroll
            for (int nt = 0; nt < 4; nt++)
                mma_tf32(oacc[nt], a, bfr[nt]);
        }
        __syncthreads();
    }

    // epilogue: O = oacc / l, tf32-rounded (feeds Wo GEMM)
    {
        float inv0 = 1.f / l_s[r0];
        float inv1 = 1.f / l_s[r0 + 8];
        size_t row0 = base + (size_t)(qb * 64 + r0) * D_MODEL;
        size_t row1 = base + (size_t)(qb * 64 + r0 + 8) * D_MODEL;
        #pragma unroll
        for (int nt = 0; nt < 4; nt++) {
            int col = warpN * 32 + nt * 8 + 2 * t;
            float2 o0 = make_float2(tf32_rna(oacc[nt][0] * inv0),
                                    tf32_rna(oacc[nt][1] * inv0));
            float2 o1 = make_float2(tf32_rna(oacc[nt][2] * inv1),
                                    tf32_rna(oacc[nt][3] * inv1));
            *(float2*)(O + row0 + col) = o0;
            *(float2*)(O + row1 + col) = o1;
        }
    }
}

// ---------------------------------------------------------------------------
// Host launcher
// ---------------------------------------------------------------------------
extern "C" void kernel_launch(void* const* d_in, const int* in_sizes, int n_in,
                              void* d_out, int out_size)
{
    const float* x     = (const float*)d_in[0];
    const float* ln1_w = (const float*)d_in[1];
    const float* ln1_b = (const float*)d_in[2];
    const float* Wq    = (const float*)d_in[3];
    const float* bq    = (const float*)d_in[4];
    const float* Wk    = (const float*)d_in[5];
    const float* bk    = (const float*)d_in[6];
    const float* Wv    = (const float*)d_in[7];
    const float* bv    = (const float*)d_in[8];
    const float* Wo    = (const float*)d_in[9];
    const float* bo    = (const float*)d_in[10];
    const float* ln2_w = (const float*)d_in[11];
    const float* ln2_b = (const float*)d_in[12];
    const float* W1    = (const float*)d_in[13];
    const float* b1    = (const float*)d_in[14];
    const float* W2    = (const float*)d_in[15];
    const float* b2    = (const float*)d_in[16];
    float* out = (float*)d_out;

    float *p_h, *p_q, *p_k, *p_v, *p_ctx, *p_x1, *p_h2, *p_ff;
    float *p_wqt, *p_wkt, *p_wvt, *p_wot, *p_w1t, *p_w2t;
    cudaGetSymbolAddress((void**)&p_h,   g_h);
    cudaGetSymbolAddress((void**)&p_q,   g_q);
    cudaGetSymbolAddress((void**)&p_k,   g_k);
    cudaGetSymbolAddress((void**)&p_v,   g_v);
    cudaGetSymbolAddress((void**)&p_ctx, g_ctx);
    cudaGetSymbolAddress((void**)&p_x1,  g_x1);
    cudaGetSymbolAddress((void**)&p_h2,  g_h2);
    cudaGetSymbolAddress((void**)&p_ff,  g_ff);
    cudaGetSymbolAddress((void**)&p_wqt, g_wqt);
    cudaGetSymbolAddress((void**)&p_wkt, g_wkt);
    cudaGetSymbolAddress((void**)&p_wvt, g_wvt);
    cudaGetSymbolAddress((void**)&p_wot, g_wot);
    cudaGetSymbolAddress((void**)&p_w1t, g_w1t);
    cudaGetSymbolAddress((void**)&p_w2t, g_w2t);

    cudaFuncSetAttribute(attn_mma_kernel,
                         cudaFuncAttributeMaxDynamicSharedMemorySize,
                         ATT_SMEM_BYTES);

    // weight transposes (+ tf32 rounding)
    transpose_rna_kernel<<<dim3(D_MODEL/32, D_MODEL/32), 256>>>(Wq, p_wqt, D_MODEL, D_MODEL);
    transpose_rna_kernel<<<dim3(D_MODEL/32, D_MODEL/32), 256>>>(Wk, p_wkt, D_MODEL, D_MODEL);
    transpose_rna_kernel<<<dim3(D_MODEL/32, D_MODEL/32), 256>>>(Wv, p_wvt, D_MODEL, D_MODEL);
    transpose_rna_kernel<<<dim3(D_MODEL/32, D_MODEL/32), 256>>>(Wo, p_wot, D_MODEL, D_MODEL);
    transpose_rna_kernel<<<dim3(D_FF/32,    D_MODEL/32), 256>>>(W1, p_w1t, D_MODEL, D_FF);
    transpose_rna_kernel<<<dim3(D_MODEL/32, D_FF/32),    256>>>(W2, p_w2t, D_FF,    D_MODEL);

    // 1. h = LN1(x)  (tf32-rounded output)
    layernorm_kernel<<<M_ROWS, 256>>>(x, ln1_w, ln1_b, p_h);

    // 2. q/k/v projections (tensor cores)
    {
        dim3 grid(D_MODEL / 128, M_ROWS / 128);
        mgemm_kernel<false, false, false><<<grid, 256>>>(p_h, p_wqt, bq, nullptr, p_q, M_ROWS, D_MODEL, D_MODEL);
        mgemm_kernel<false, false, false><<<grid, 256>>>(p_h, p_wkt, bk, nullptr, p_k, M_ROWS, D_MODEL, D_MODEL);
        mgemm_kernel<false, false, false><<<grid, 256>>>(p_h, p_wvt, bv, nullptr, p_v, M_ROWS, D_MODEL, D_MODEL);
    }

    // 3. attention -> ctx (tensor cores, tf32-rounded output)
    {
        dim3 grid(S_ / 64, N_HEADS, B_);
        attn_mma_kernel<<<grid, 256, ATT_SMEM_BYTES>>>(p_q, p_k, p_v, p_ctx);
    }

    // 4. x1 = x + ctx @ Wo + bo
    {
        dim3 grid(D_MODEL / 128, M_ROWS / 128);
        mgemm_kernel<false, true, false><<<grid, 256>>>(p_ctx, p_wot, bo, x, p_x1, M_ROWS, D_MODEL, D_MODEL);
    }

    // 5. h2 = LN2(x1)  (tf32-rounded output)
    layernorm_kernel<<<M_ROWS, 256>>>(p_x1, ln2_w, ln2_b, p_h2);

    // 6. ff = relu(h2 @ W1 + b1)  (tf32-rounded output; feeds FFN2)
    {
        dim3 grid(D_FF / 128, M_ROWS / 128);
        mgemm_kernel<true, false, true><<<grid, 256>>>(p_h2, p_w1t, b1, nullptr, p_ff, M_ROWS, D_FF, D_MODEL);
    }

    // 7. out = x1 + ff @ W2 + b2
    {
        dim3 grid(D_MODEL / 128, M_ROWS / 128);
        mgemm_kernel<false, true, false><<<grid, 256>>>(p_ff, p_w2t, b2, p_x1, out, M_ROWS, D_MODEL, D_FF);
    }
}

// round 17
// speedup vs baseline: 2.4298x; 1.1027x over previous
#include <cuda_runtime.h>
#include <cstdint>

// ---------------------------------------------------------------------------
// TransformerBlock: B=2, S=2048, D=1024, H=16, Dk=64, Dff=4096, fp32
// Round 17 (resubmit of R12 — five infra timeouts, never measured):
// R11 verified (1760us). This round: cp.async 3-stage pipeline in mgemm;
// register-prefetch of K/V tiles in attention; QKV rounding moved to GEMM
// epilogue (bit-identical) so attention loads are plain copies.
// ---------------------------------------------------------------------------

#define D_MODEL 1024
#define N_HEADS 16
#define D_K     64
#define D_FF    4096
#define B_      2
#define S_      2048
#define M_ROWS  (B_ * S_)          // 4096

// ---------------- scratch (device globals; no allocations allowed) ----------
__device__ float g_h  [M_ROWS * D_MODEL];
__device__ float g_q  [M_ROWS * D_MODEL];
__device__ float g_k  [M_ROWS * D_MODEL];
__device__ float g_v  [M_ROWS * D_MODEL];
__device__ float g_ctx[M_ROWS * D_MODEL];
__device__ float g_x1 [M_ROWS * D_MODEL];
__device__ float g_h2 [M_ROWS * D_MODEL];
__device__ float g_ff [M_ROWS * D_FF];
// transposed (and tf32-rounded) weights: Wt[n][k] = rna(W[k][n])
__device__ float g_wqt[D_MODEL * D_MODEL];
__device__ float g_wkt[D_MODEL * D_MODEL];
__device__ float g_wvt[D_MODEL * D_MODEL];
__device__ float g_wot[D_MODEL * D_MODEL];
__device__ float g_w1t[D_FF * D_MODEL];
__device__ float g_w2t[D_MODEL * D_FF];

__device__ __forceinline__ float tf32_rna(float x) {
    uint32_t u;
    asm("cvt.rna.tf32.f32 %0, %1;" : "=r"(u) : "f"(x));
    return __uint_as_float(u);
}

__device__ __forceinline__ uint32_t smem_u32(const void* p) {
    uint32_t a;
    asm("{ .reg .u64 t; cvta.to.shared.u64 t, %1; cvt.u32.u64 %0, t; }"
        : "=r"(a) : "l"(p));
    return a;
}

#define CP_ASYNC16(dst, src) \
    asm volatile("cp.async.ca.shared.global [%0], [%1], 16;" \
        :: "r"(dst), "l"(src) : "memory")
#define CP_COMMIT() asm volatile("cp.async.commit_group;" ::: "memory")
#define CP_WAIT1()  asm volatile("cp.async.wait_group 1;"  ::: "memory")

__device__ __forceinline__ void mma_tf32(float c[4], const uint32_t a[4],
                                         const uint32_t b[2]) {
    asm volatile(
        "mma.sync.aligned.m16n8k8.row.col.f32.tf32.tf32.f32 "
        "{%0,%1,%2,%3}, {%4,%5,%6,%7}, {%8,%9}, {%0,%1,%2,%3};"
        : "+f"(c[0]), "+f"(c[1]), "+f"(c[2]), "+f"(c[3])
        : "r"(a[0]), "r"(a[1]), "r"(a[2]), "r"(a[3]), "r"(b[0]), "r"(b[1]));
}

// ---------------------------------------------------------------------------
// Fused transpose + tf32-round: Wt[n][k] = rna(W[k][n]),  W is [K,N] row-major
// ---------------------------------------------------------------------------
__global__ __launch_bounds__(256) void transpose_rna_kernel(
    const float* __restrict__ W, float* __restrict__ Wt, int K, int N)
{
    __shared__ float t[32][33];
    int n0 = blockIdx.x * 32, k0 = blockIdx.y * 32;
    int tx = threadIdx.x & 31, ty = threadIdx.x >> 5;  // 32 x 8
    #pragma unroll
    for (int i = 0; i < 4; i++)
        t[ty + 8 * i][tx] = W[(size_t)(k0 + ty + 8 * i) * N + n0 + tx];
    __syncthreads();
    #pragma unroll
    for (int i = 0; i < 4; i++)
        Wt[(size_t)(n0 + ty + 8 * i) * K + k0 + tx] = tf32_rna(t[tx][ty + 8 * i]);
}

// ---------------------------------------------------------------------------
// TF32 tensor-core GEMM: C[M,N] = A[M,K] @ Wt[N,K]^T + bias (+res) (+relu)
// 128x128/CTA, 8 warps (2x4), warp tile 64x32, BK=16.
// 3-stage cp.async pipeline into dynamic smem (61.4 KB).
// A and Wt values must already be tf32-rounded (done at producers).
// ---------------------------------------------------------------------------
#define SPAD 20
#define G_STAGES 3
#define G_STAGE_FLOATS (128 * SPAD)
#define G_SMEM_BYTES (G_STAGES * G_STAGE_FLOATS * 2 * 4)   // 61440

template<bool RELU, bool RES, bool RNA>
__global__ __launch_bounds__(256, 2) void mgemm_kernel(
    const float* __restrict__ A, const float* __restrict__ Wt,
    const float* __restrict__ bias, const float* __restrict__ res,
    float* __restrict__ C, int M, int N, int K)
{
    extern __shared__ float gsm[];

    const int tid = threadIdx.x, lane = tid & 31, wid = tid >> 5;
    const int warpM = wid & 1, warpN = wid >> 1;     // 2 x 4
    const int g = lane >> 2, t = lane & 3;
    const int m0 = blockIdx.y * 128, n0 = blockIdx.x * 128;

    const int lrow = tid >> 1;            // 0..127
    const int lcg  = (tid & 1) * 8;       // 0 or 8

    const uint32_t sbase = smem_u32(gsm);
    const float* Ag = A  + (size_t)(m0 + lrow) * K + lcg;
    const float* Bg = Wt + (size_t)(n0 + lrow) * K + lcg;
    const uint32_t a_dst0 = sbase + (uint32_t)(lrow * SPAD + lcg) * 4u;
    const uint32_t b_dst0 = a_dst0 + (uint32_t)(G_STAGES * G_STAGE_FLOATS) * 4u;

    float c[4][4][4];
    #pragma unroll
    for (int i = 0; i < 4; i++)
        #pragma unroll
        for (int j = 0; j < 4; j++)
            #pragma unroll
            for (int r = 0; r < 4; r++) c[i][j][r] = 0.f;

    auto issue_stage = [&](int s, int cidx) {
        const float* ap = Ag + cidx * 16;
        const float* bp = Bg + cidx * 16;
        uint32_t ad = a_dst0 + (uint32_t)(s * G_STAGE_FLOATS) * 4u;
        uint32_t bd = b_dst0 + (uint32_t)(s * G_STAGE_FLOATS) * 4u;
        CP_ASYNC16(ad,      ap);
        CP_ASYNC16(ad + 16, ap + 4);
        CP_ASYNC16(bd,      bp);
        CP_ASYNC16(bd + 16, bp + 4);
        CP_COMMIT();
    };

    const int nch = K >> 4;   // >= 64 always here
    issue_stage(0, 0);
    issue_stage(1, 1);

    for (int it = 0; it < nch; ++it) {
        const int s = it % G_STAGES;
        CP_WAIT1();
        __syncthreads();

        const float (*As)[SPAD] = (const float(*)[SPAD])(gsm + s * G_STAGE_FLOATS);
        const float (*Bs)[SPAD] = (const float(*)[SPAD])(gsm + (G_STAGES + s) * G_STAGE_FLOATS);

        #pragma unroll
        for (int kk = 0; kk < 16; kk += 8) {
            uint32_t a[4][4], b[4][2];
            #pragma unroll
            for (int mt = 0; mt < 4; mt++) {
                int row = warpM * 64 + mt * 16 + g;
                a[mt][0] = __float_as_uint(As[row]    [kk + t]);
                a[mt][1] = __float_as_uint(As[row + 8][kk + t]);
                a[mt][2] = __float_as_uint(As[row]    [kk + t + 4]);
                a[mt][3] = __float_as_uint(As[row + 8][kk + t + 4]);
            }
            #pragma unroll
            for (int nt = 0; nt < 4; nt++) {
                int n = warpN * 32 + nt * 8 + g;
                b[nt][0] = __float_as_uint(Bs[n][kk + t]);
                b[nt][1] = __float_as_uint(Bs[n][kk + t + 4]);
            }
            #pragma unroll
            for (int mt = 0; mt < 4; mt++)
                #pragma unroll
                for (int nt = 0; nt < 4; nt++)
                    mma_tf32(c[mt][nt], a[mt], b[nt]);
        }

        const int c2 = it + 2;
        if (c2 < nch) issue_stage(c2 % G_STAGES, c2);
    }

    // epilogue
    #pragma unroll
    for (int mt = 0; mt < 4; mt++) {
        #pragma unroll
        for (int nt = 0; nt < 4; nt++) {
            int row = m0 + warpM * 64 + mt * 16 + g;
            int col = n0 + warpN * 32 + nt * 8 + t * 2;
            float b0 = bias[col], b1 = bias[col + 1];
            float v00 = c[mt][nt][0] + b0, v01 = c[mt][nt][1] + b1;
            float v10 = c[mt][nt][2] + b0, v11 = c[mt][nt][3] + b1;
            if (RES) {
                float2 r0 = *(const float2*)(res + (size_t)row * N + col);
                float2 r1 = *(const float2*)(res + (size_t)(row + 8) * N + col);
                v00 += r0.x; v01 += r0.y; v10 += r1.x; v11 += r1.y;
            }
            if (RELU) {
                v00 = fmaxf(v00, 0.f); v01 = fmaxf(v01, 0.f);
                v10 = fmaxf(v10, 0.f); v11 = fmaxf(v11, 0.f);
            }
            if (RNA) {
                v00 = tf32_rna(v00); v01 = tf32_rna(v01);
                v10 = tf32_rna(v10); v11 = tf32_rna(v11);
            }
            float2 o0 = make_float2(v00, v01);
            float2 o1 = make_float2(v10, v11);
            *(float2*)(C + (size_t)row * N + col)       = o0;
            *(float2*)(C + (size_t)(row + 8) * N + col) = o1;
        }
    }
}

// ---------------------------------------------------------------------------
// LayerNorm: one block per row; output tf32-rounded (feeds GEMMs only)
// ---------------------------------------------------------------------------
__global__ __launch_bounds__(256) void layernorm_kernel(
    const float* __restrict__ x, const float* __restrict__ w,
    const float* __restrict__ b, float* __restrict__ out)
{
    int row = blockIdx.x;
    const float* xr = x + (long)row * D_MODEL;
    int c = threadIdx.x * 4;
    float4 v = *(const float4*)(xr + c);
    float s  = v.x + v.y + v.z + v.w;
    float ss = v.x*v.x + v.y*v.y + v.z*v.z + v.w*v.w;

    #pragma unroll
    for (int o = 16; o > 0; o >>= 1) {
        s  += __shfl_xor_sync(0xffffffffu, s,  o);
        ss += __shfl_xor_sync(0xffffffffu, ss, o);
    }
    __shared__ float rs[8], rss[8];
    int wid = threadIdx.x >> 5, lane = threadIdx.x & 31;
    if (lane == 0) { rs[wid] = s; rss[wid] = ss; }
    __syncthreads();
    s = 0.f; ss = 0.f;
    #pragma unroll
    for (int i = 0; i < 8; i++) { s += rs[i]; ss += rss[i]; }

    float mu  = s * (1.0f / D_MODEL);
    float var = ss * (1.0f / D_MODEL) - mu * mu;
    float rstd = rsqrtf(var + 1e-5f);

    float4 wv = *(const float4*)(w + c);
    float4 bv = *(const float4*)(b + c);
    float4 o4;
    o4.x = tf32_rna((v.x - mu) * rstd * wv.x + bv.x);
    o4.y = tf32_rna((v.y - mu) * rstd * wv.y + bv.y);
    o4.z = tf32_rna((v.z - mu) * rstd * wv.z + bv.z);
    o4.w = tf32_rna((v.w - mu) * rstd * wv.w + bv.w);
    *(float4*)(out + (long)row * D_MODEL + c) = o4;
}

// ---------------------------------------------------------------------------
// Tensor-core flash attention: BQ=64, BKV=64, mma.sync tf32 (verified R11).
// This round: K/V tiles register-prefetched across the compute phase.
// Q/K/V arrive pre-rounded (QKV GEMM epilogue does rna) -> plain copies.
// ---------------------------------------------------------------------------
#define AST 68
#define ATT_SMEM_BYTES (4 * 64 * AST * 4 + 3 * 64 * 4)   // 70400

__global__ __launch_bounds__(256) void attn_mma_kernel(
    const float* __restrict__ Q, const float* __restrict__ K,
    const float* __restrict__ V, float* __restrict__ O)
{
    extern __shared__ float sm[];
    float (*Qs)[AST] = (float(*)[AST])(sm);
    float (*Ks)[AST] = (float(*)[AST])(sm + 64 * AST);
    float (*Vs)[AST] = (float(*)[AST])(sm + 2 * 64 * AST);
    float (*Ss)[AST] = (float(*)[AST])(sm + 3 * 64 * AST);
    float* m_s = sm + 4 * 64 * AST;
    float* l_s = m_s + 64;
    float* a_s = l_s + 64;

    const int qb = blockIdx.x, h = blockIdx.y, b = blockIdx.z;
    const int tid = threadIdx.x, lane = tid & 31, wid = tid >> 5;
    const int warpM = wid >> 1, warpN = wid & 1;   // 4 x 2
    const int g = lane >> 2, t = lane & 3;
    const int r0 = warpM * 16 + g;                 // fragment row (and r0+8)
    const float scale = 0.125f;                    // 1/sqrt(64)

    const size_t base = ((size_t)b * S_) * D_MODEL + h * D_K;
    const int lrow = tid >> 2;            // 0..63
    const int lc0  = (tid & 3) * 16;      // 0,16,32,48

    // load Q tile 64x64 (pre-rounded) + first K/V tile
    {
        const float* qp = Q + base + (size_t)(qb * 64 + lrow) * D_MODEL + lc0;
        const float* kp = K + base + (size_t)lrow * D_MODEL + lc0;
        const float* vp = V + base + (size_t)lrow * D_MODEL + lc0;
        #pragma unroll
        for (int u = 0; u < 4; u++) {
            *(float4*)&Qs[lrow][lc0 + u*4] = *(const float4*)(qp + u * 4);
            *(float4*)&Ks[lrow][lc0 + u*4] = *(const float4*)(kp + u * 4);
            *(float4*)&Vs[lrow][lc0 + u*4] = *(const float4*)(vp + u * 4);
        }
    }
    if (tid < 64) { m_s[tid] = -1e30f; l_s[tid] = 0.f; }

    float oacc[4][4];
    #pragma unroll
    for (int nt = 0; nt < 4; nt++)
        #pragma unroll
        for (int i = 0; i < 4; i++) oacc[nt][i] = 0.f;

    __syncthreads();

    for (int j0 = 0; j0 < S_; j0 += 64) {
        const bool more = (j0 + 64) < S_;
        float4 kn[4], vn[4];
        if (more) {
            const float* kp = K + base + (size_t)(j0 + 64 + lrow) * D_MODEL + lc0;
            const float* vp = V + base + (size_t)(j0 + 64 + lrow) * D_MODEL + lc0;
            #pragma unroll
            for (int u = 0; u < 4; u++) {
                kn[u] = *(const float4*)(kp + u * 4);
                vn[u] = *(const float4*)(vp + u * 4);
            }
        }

        // S = Q @ K^T  (warp tile 16x32)
        float sacc[4][4];
        #pragma unroll
        for (int nt = 0; nt < 4; nt++)
            #pragma unroll
            for (int i = 0; i < 4; i++) sacc[nt][i] = 0.f;

        #pragma unroll
        for (int kk = 0; kk < 64; kk += 8) {
            uint32_t a[4], bfr[4][2];
            a[0] = __float_as_uint(Qs[r0]    [kk + t]);
            a[1] = __float_as_uint(Qs[r0 + 8][kk + t]);
            a[2] = __float_as_uint(Qs[r0]    [kk + t + 4]);
            a[3] = __float_as_uint(Qs[r0 + 8][kk + t + 4]);
            #pragma unroll
            for (int nt = 0; nt < 4; nt++) {
                int n = warpN * 32 + nt * 8 + g;
                bfr[nt][0] = __float_as_uint(Ks[n][kk + t]);
                bfr[nt][1] = __float_as_uint(Ks[n][kk + t + 4]);
            }
            #pragma unroll
            for (int nt = 0; nt < 4; nt++)
                mma_tf32(sacc[nt], a, bfr[nt]);
        }
        #pragma unroll
        for (int nt = 0; nt < 4; nt++) {
            int col = warpN * 32 + nt * 8 + 2 * t;
            Ss[r0]    [col]     = sacc[nt][0] * scale;
            Ss[r0]    [col + 1] = sacc[nt][1] * scale;
            Ss[r0 + 8][col]     = sacc[nt][2] * scale;
            Ss[r0 + 8][col + 1] = sacc[nt][3] * scale;
        }
        __syncthreads();

        // online softmax: 4 threads per row, 16 cols each
        {
            int r = tid >> 2, sub = tid & 3;
            float mx = -1e30f;
            #pragma unroll
            for (int j = 0; j < 16; j++) mx = fmaxf(mx, Ss[r][sub * 16 + j]);
            mx = fmaxf(mx, __shfl_xor_sync(0xffffffffu, mx, 1));
            mx = fmaxf(mx, __shfl_xor_sync(0xffffffffu, mx, 2));
            float mo = m_s[r];
            float mn = fmaxf(mo, mx);
            float ls = 0.f;
            #pragma unroll
            for (int j = 0; j < 16; j++) {
                float p = __expf(Ss[r][sub * 16 + j] - mn);
                Ss[r][sub * 16 + j] = tf32_rna(p);
                ls += p;
            }
            ls += __shfl_xor_sync(0xffffffffu, ls, 1);
            ls += __shfl_xor_sync(0xffffffffu, ls, 2);
            if (sub == 0) {
                float al = __expf(mo - mn);
                m_s[r] = mn;
                l_s[r] = l_s[r] * al + ls;
                a_s[r] = al;
            }
        }
        __syncthreads();

        // rescale O and accumulate P @ V
        {
            float al0 = a_s[r0], al1 = a_s[r0 + 8];
            #pragma unroll
            for (int nt = 0; nt < 4; nt++) {
                oacc[nt][0] *= al0; oacc[nt][1] *= al0;
                oacc[nt][2] *= al1; oacc[nt][3] *= al1;
            }
        }
        #pragma unroll
        for (int kk = 0; kk < 64; kk += 8) {
            uint32_t a[4], bfr[4][2];
            a[0] = __float_as_uint(Ss[r0]    [kk + t]);
            a[1] = __float_as_uint(Ss[r0 + 8][kk + t]);
            a[2] = __float_as_uint(Ss[r0]    [kk + t + 4]);
            a[3] = __float_as_uint(Ss[r0 + 8][kk + t + 4]);
            #pragma unroll
            for (int nt = 0; nt < 4; nt++) {
                int n = warpN * 32 + nt * 8 + g;
                bfr[nt][0] = __float_as_uint(Vs[kk + t]    [n]);
                bfr[nt][1] = __float_as_uint(Vs[kk + t + 4][n]);
            }
            #pragma unroll
            for (int nt = 0; nt < 4; nt++)
                mma_tf32(oacc[nt], a, bfr[nt]);
        }
        __syncthreads();

        // store prefetched K/V for next iteration
        if (more) {
            #pragma unroll
            for (int u = 0; u < 4; u++) {
                *(float4*)&Ks[lrow][lc0 + u*4] = kn[u];
                *(float4*)&Vs[lrow][lc0 + u*4] = vn[u];
            }
            __syncthreads();
        }
    }

    // epilogue: O = oacc / l, tf32-rounded (feeds Wo GEMM)
    {
        float inv0 = 1.f / l_s[r0];
        float inv1 = 1.f / l_s[r0 + 8];
        size_t row0 = base + (size_t)(qb * 64 + r0) * D_MODEL;
        size_t row1 = base + (size_t)(qb * 64 + r0 + 8) * D_MODEL;
        #pragma unroll
        for (int nt = 0; nt < 4; nt++) {
            int col = warpN * 32 + nt * 8 + 2 * t;
            float2 o0 = make_float2(tf32_rna(oacc[nt][0] * inv0),
                                    tf32_rna(oacc[nt][1] * inv0));
            float2 o1 = make_float2(tf32_rna(oacc[nt][2] * inv1),
                                    tf32_rna(oacc[nt][3] * inv1));
            *(float2*)(O + row0 + col) = o0;
            *(float2*)(O + row1 + col) = o1;
        }
    }
}

// ---------------------------------------------------------------------------
// Host launcher
// ---------------------------------------------------------------------------
extern "C" void kernel_launch(void* const* d_in, const int* in_sizes, int n_in,
                              void* d_out, int out_size)
{
    const float* x     = (const float*)d_in[0];
    const float* ln1_w = (const float*)d_in[1];
    const float* ln1_b = (const float*)d_in[2];
    const float* Wq    = (const float*)d_in[3];
    const float* bq    = (const float*)d_in[4];
    const float* Wk    = (const float*)d_in[5];
    const float* bk    = (const float*)d_in[6];
    const float* Wv    = (const float*)d_in[7];
    const float* bv    = (const float*)d_in[8];
    const float* Wo    = (const float*)d_in[9];
    const float* bo    = (const float*)d_in[10];
    const float* ln2_w = (const float*)d_in[11];
    const float* ln2_b = (const float*)d_in[12];
    const float* W1    = (const float*)d_in[13];
    const float* b1    = (const float*)d_in[14];
    const float* W2    = (const float*)d_in[15];
    const float* b2    = (const float*)d_in[16];
    float* out = (float*)d_out;

    float *p_h, *p_q, *p_k, *p_v, *p_ctx, *p_x1, *p_h2, *p_ff;
    float *p_wqt, *p_wkt, *p_wvt, *p_wot, *p_w1t, *p_w2t;
    cudaGetSymbolAddress((void**)&p_h,   g_h);
    cudaGetSymbolAddress((void**)&p_q,   g_q);
    cudaGetSymbolAddress((void**)&p_k,   g_k);
    cudaGetSymbolAddress((void**)&p_v,   g_v);
    cudaGetSymbolAddress((void**)&p_ctx, g_ctx);
    cudaGetSymbolAddress((void**)&p_x1,  g_x1);
    cudaGetSymbolAddress((void**)&p_h2,  g_h2);
    cudaGetSymbolAddress((void**)&p_ff,  g_ff);
    cudaGetSymbolAddress((void**)&p_wqt, g_wqt);
    cudaGetSymbolAddress((void**)&p_wkt, g_wkt);
    cudaGetSymbolAddress((void**)&p_wvt, g_wvt);
    cudaGetSymbolAddress((void**)&p_wot, g_wot);
    cudaGetSymbolAddress((void**)&p_w1t, g_w1t);
    cudaGetSymbolAddress((void**)&p_w2t, g_w2t);

    cudaFuncSetAttribute(attn_mma_kernel,
                         cudaFuncAttributeMaxDynamicSharedMemorySize,
                         ATT_SMEM_BYTES);
    cudaFuncSetAttribute(mgemm_kernel<false, false, false>,
                         cudaFuncAttributeMaxDynamicSharedMemorySize, G_SMEM_BYTES);
    cudaFuncSetAttribute(mgemm_kernel<false, false, true>,
                         cudaFuncAttributeMaxDynamicSharedMemorySize, G_SMEM_BYTES);
    cudaFuncSetAttribute(mgemm_kernel<false, true, false>,
                         cudaFuncAttributeMaxDynamicSharedMemorySize, G_SMEM_BYTES);
    cudaFuncSetAttribute(mgemm_kernel<true, false, true>,
                         cudaFuncAttributeMaxDynamicSharedMemorySize, G_SMEM_BYTES);

    // weight transposes (+ tf32 rounding)
    transpose_rna_kernel<<<dim3(D_MODEL/32, D_MODEL/32), 256>>>(Wq, p_wqt, D_MODEL, D_MODEL);
    transpose_rna_kernel<<<dim3(D_MODEL/32, D_MODEL/32), 256>>>(Wk, p_wkt, D_MODEL, D_MODEL);
    transpose_rna_kernel<<<dim3(D_MODEL/32, D_MODEL/32), 256>>>(Wv, p_wvt, D_MODEL, D_MODEL);
    transpose_rna_kernel<<<dim3(D_MODEL/32, D_MODEL/32), 256>>>(Wo, p_wot, D_MODEL, D_MODEL);
    transpose_rna_kernel<<<dim3(D_FF/32,    D_MODEL/32), 256>>>(W1, p_w1t, D_MODEL, D_FF);
    transpose_rna_kernel<<<dim3(D_MODEL/32, D_FF/32),    256>>>(W2, p_w2t, D_FF,    D_MODEL);

    // 1. h = LN1(x)  (tf32-rounded output)
    layernorm_kernel<<<M_ROWS, 256>>>(x, ln1_w, ln1_b, p_h);

    // 2. q/k/v projections (tensor cores; rna epilogue so attention copies plainly)
    {
        dim3 grid(D_MODEL / 128, M_ROWS / 128);
        mgemm_kernel<false, false, true><<<grid, 256, G_SMEM_BYTES>>>(p_h, p_wqt, bq, nullptr, p_q, M_ROWS, D_MODEL, D_MODEL);
        mgemm_kernel<false, false, true><<<grid, 256, G_SMEM_BYTES>>>(p_h, p_wkt, bk, nullptr, p_k, M_ROWS, D_MODEL, D_MODEL);
        mgemm_kernel<false, false, true><<<grid, 256, G_SMEM_BYTES>>>(p_h, p_wvt, bv, nullptr, p_v, M_ROWS, D_MODEL, D_MODEL);
    }

    // 3. attention -> ctx (tensor cores, tf32-rounded output)
    {
        dim3 grid(S_ / 64, N_HEADS, B_);
        attn_mma_kernel<<<grid, 256, ATT_SMEM_BYTES>>>(p_q, p_k, p_v, p_ctx);
    }

    // 4. x1 = x + ctx @ Wo + bo
    {
        dim3 grid(D_MODEL / 128, M_ROWS / 128);
        mgemm_kernel<false, true, false><<<grid, 256, G_SMEM_BYTES>>>(p_ctx, p_wot, bo, x, p_x1, M_ROWS, D_MODEL, D_MODEL);
    }

    // 5. h2 = LN2(x1)  (tf32-rounded output)
    layernorm_kernel<<<M_ROWS, 256>>>(p_x1, ln2_w, ln2_b, p_h2);

    // 6. ff = relu(h2 @ W1 + b1)  (tf32-rounded output; feeds FFN2)
    {
        dim3 grid(D_FF / 128, M_ROWS / 128);
        mgemm_kernel<true, false, true><<<grid, 256, G_SMEM_BYTES>>>(p_h2, p_w1t, b1, nullptr, p_ff, M_ROWS, D_FF, D_MODEL);
    }

    // 7. out = x1 + ff @ W2 + b2
    {
        dim3 grid(D_MODEL / 128, M_ROWS / 128);
        mgemm_kernel<false, true, false><<<grid, 256, G_SMEM_BYTES>>>(p_ff, p_w2t, b2, p_x1, out, M_ROWS, D_MODEL, D_FF);
    }
}